// round 6
// baseline (speedup 1.0000x reference)
#include <cuda_runtime.h>
#include <math.h>

#define NB 8
#define NH 256
#define NW 256
#define NPIX (NB*NH*NW)
#define NCH 8              // 8 chunks of 32 rows
#define BLKB 64            // k_loss blocks per batch
#define NLB (NB*BLKB)      // 512 loss blocks

// Scratch (__device__ globals per allocation rules)
__device__ unsigned g_bits[NB*NCH*NW];   // bit i of [b][c][j] = (mask(c*32+i, j) != 0)
__device__ float    g_absd[NPIX];        // |dist| = fgd + bgd (one of them is 0)
__device__ float2   g_rowmax[NB*NH];     // per-row (fg_max, bg_max)
__device__ float    g_part[NLB*12];      // per-block partials: [0:4) focal, [4:8) inter, [8:12) (p+t)w
__device__ unsigned g_ctr = 0;           // ticket counter (reset by last block each call)

// ---------------------------------------------------------------------------
// Pack mask into per-column bitsets via warp ballot transpose.
// 128 blocks x 128 threads = 512 warps; one warp per 32x32 tile. MLP=32 loads.
__global__ void k_pack(const int* __restrict__ tg) {
    int w    = blockIdx.x * 4 + (threadIdx.x >> 5);  // 512 warps
    int lane = threadIdx.x & 31;
    int b = w >> 6, rem = w & 63, c = rem >> 3, jg = rem & 7;
    int j = jg * 32 + lane;
    const int* base = tg + (b * NH + c * 32) * NW + j;
    int v[32];
    #pragma unroll
    for (int i = 0; i < 32; ++i) v[i] = __ldg(base + i * NW);
    unsigned word = 0u;
    #pragma unroll
    for (int i = 0; i < 32; ++i) {
        unsigned bal = __ballot_sync(0xffffffffu, v[i] != 0);
        word |= ((bal >> lane) & 1u) << i;
    }
    g_bits[(b * NCH + c) * NW + j] = word;
}

// Vertical distance to nearest set bit (after XOR with inv) in column jo at row h.
__device__ __forceinline__ float vdist(const unsigned* sw, int jo, int h,
                                       int c0, int b0, unsigned inv) {
    unsigned m = (sw[c0 * NW + jo] ^ inv) & (0xFFFFFFFFu >> (31 - b0));
    int c = c0;
    while (m == 0u && c > 0) m = sw[--c * NW + jo] ^ inv;
    int du = m ? h - (c * 32 + 31 - __clz(m)) : 100000;
    m = (sw[c0 * NW + jo] ^ inv) & (0xFFFFFFFFu << b0);
    c = c0;
    while (m == 0u && c < NCH - 1) m = sw[++c * NW + jo] ^ inv;
    int dd = m ? (c * 32 + __ffs(m) - 1) - h : 100000;
    int d = min(du, dd);
    return (d >= 100000) ? 1e6f : (float)d;
}

// ---------------------------------------------------------------------------
// EDT: one block per (b, h) row (max parallelism).
__global__ void k_edt() {
    int blk = blockIdx.x;
    int b = blk >> 8, h = blk & 255;
    int jo = threadIdx.x;
    __shared__ unsigned sw[NCH * NW];
    __shared__ float sf[NW], sb[NW];
    #pragma unroll
    for (int c = 0; c < NCH; ++c)
        sw[c * NW + jo] = g_bits[(b * NCH + c) * NW + jo];
    __syncthreads();

    int c0 = h >> 5, b0 = h & 31;
    float gf = vdist(sw, jo, h, c0, b0, 0xFFFFFFFFu);  // fg: mask==0
    float gb = vdist(sw, jo, h, c0, b0, 0u);           // bg: mask==1
    sf[jo] = gf;
    sb[jo] = gb;
    __syncthreads();

    float bf = gf * gf;
    float bb = gb * gb;
    for (int r = 1; r < NW; ++r) {
        float c = (float)(r * r);
        if (c >= bf && c >= bb) break;
        int jl = jo - r, jr = jo + r;
        if (jl >= 0) {
            float a = sf[jl], x = sb[jl];
            bf = fminf(bf, a * a + c);
            bb = fminf(bb, x * x + c);
        }
        if (jr < NW) {
            float a = sf[jr], x = sb[jr];
            bf = fminf(bf, a * a + c);
            bb = fminf(bb, x * x + c);
        }
    }
    float fgd = sqrtf(bf);
    float bgd = sqrtf(bb);
    g_absd[(b * NH + h) * NW + jo] = fgd + bgd;

    float mf = fgd, mb = bgd;
    #pragma unroll
    for (int o = 16; o; o >>= 1) {
        mf = fmaxf(mf, __shfl_down_sync(0xffffffffu, mf, o));
        mb = fmaxf(mb, __shfl_down_sync(0xffffffffu, mb, o));
    }
    __shared__ float smf[8], smb[8];
    int lane = jo & 31, wq = jo >> 5;
    if (lane == 0) { smf[wq] = mf; smb[wq] = mb; }
    __syncthreads();
    if (jo == 0) {
        #pragma unroll
        for (int q = 1; q < 8; ++q) { mf = fmaxf(mf, smf[q]); mb = fmaxf(mb, smb[q]); }
        g_rowmax[blk] = make_float2(mf, mb);
    }
}

// ---------------------------------------------------------------------------
// Deterministic final combine (executed by the last k_loss block).
__device__ void final_combine(float* out, int tid, int lane, int wq) {
    __shared__ float s_iou[NB][4];
    __shared__ float sf4[4][256];
    // IoU: warp wq handles batch wq
    {
        float in_[4] = {0.f,0.f,0.f,0.f}, u_[4] = {0.f,0.f,0.f,0.f};
        for (int r = lane; r < BLKB; r += 32) {
            const float* pp = g_part + (wq * BLKB + r) * 12;
            #pragma unroll
            for (int k = 0; k < 4; ++k) { in_[k] += pp[4 + k]; u_[k] += pp[8 + k]; }
        }
        #pragma unroll
        for (int k = 0; k < 4; ++k) {
            #pragma unroll
            for (int o = 16; o; o >>= 1) {
                in_[k] += __shfl_down_sync(0xffffffffu, in_[k], o);
                u_[k]  += __shfl_down_sync(0xffffffffu, u_[k],  o);
            }
        }
        if (lane == 0) {
            #pragma unroll
            for (int k = 0; k < 4; ++k) {
                float inter = in_[k];
                float un = u_[k] - inter;
                s_iou[wq][k] = (inter + 1e-6f) / (un + 1e-6f);
            }
        }
    }

    // Focal: tree reduce over NLB block-partials
    float f[4] = {0.f,0.f,0.f,0.f};
    for (int i = tid; i < NLB; i += 256) {
        const float* pp = g_part + i * 12;
        #pragma unroll
        for (int k = 0; k < 4; ++k) f[k] += pp[k];
    }
    #pragma unroll
    for (int k = 0; k < 4; ++k) sf4[k][tid] = f[k];
    __syncthreads();
    for (int s = 128; s; s >>= 1) {
        if (tid < s) {
            #pragma unroll
            for (int k = 0; k < 4; ++k) sf4[k][tid] += sf4[k][tid + s];
        }
        __syncthreads();
    }

    if (tid == 0) {
        const float wgt[4] = { 1.0f, 0.4f, 0.2f, 0.4f / 3.0f };
        float total = 0.f;
        #pragma unroll
        for (int k = 0; k < 4; ++k) {
            float fm = sf4[k][0] / (float)NPIX;
            float is = 0.f;
            #pragma unroll
            for (int b2 = 0; b2 < NB; ++b2) is += s_iou[b2][k];
            float il = 1.f - is / (float)NB;
            total += wgt[k] * (fm + il);
        }
        out[0] = total;
        g_ctr = 0;   // reset ticket for next graph replay
    }
}

// ---------------------------------------------------------------------------
// Fused focal + IoU partials; last block performs the final combine.
__global__ void k_loss(const float* __restrict__ p0, const float* __restrict__ p1,
                       const float* __restrict__ p2, const float* __restrict__ p3,
                       const int* __restrict__ tg, float* __restrict__ out) {
    int blk = blockIdx.x;
    int b = blk >> 6;
    int tid = threadIdx.x;
    int lane = tid & 31, wq = tid >> 5;

    // batch maxima from per-row maxima (deterministic)
    __shared__ float sA[8], sB[8];
    {
        float2 rm = g_rowmax[b * NH + tid];
        float mf = rm.x, mb = rm.y;
        #pragma unroll
        for (int o = 16; o; o >>= 1) {
            mf = fmaxf(mf, __shfl_down_sync(0xffffffffu, mf, o));
            mb = fmaxf(mb, __shfl_down_sync(0xffffffffu, mb, o));
        }
        if (lane == 0) { sA[wq] = mf; sB[wq] = mb; }
    }
    __syncthreads();
    float mf = sA[0], mb = sB[0];
    #pragma unroll
    for (int q = 1; q < 8; ++q) { mf = fmaxf(mf, sA[q]); mb = fmaxf(mb, sB[q]); }
    float md = fmaxf(mf, mb);
    bool valid = (mb < 9e5f) && (md > 0.f);
    float inv3 = valid ? 3.0f / fmaxf(md, 1e-12f) : 0.f;
    float cfl  = valid ? 1.f : 0.f;

    int pix = b * (NH * NW) + (blk & 63) * 1024 + tid * 4;
    float4 x0 = *(const float4*)(p0 + pix);
    float4 x1 = *(const float4*)(p1 + pix);
    float4 x2 = *(const float4*)(p2 + pix);
    float4 x3 = *(const float4*)(p3 + pix);
    int4   tv = *(const int4*)(tg + pix);
    float4 ad = *(const float4*)(g_absd + pix);

    float X[4][4] = { {x0.x, x1.x, x2.x, x3.x},
                      {x0.y, x1.y, x2.y, x3.y},
                      {x0.z, x1.z, x2.z, x3.z},
                      {x0.w, x1.w, x2.w, x3.w} };
    float T[4]  = { (float)tv.x, (float)tv.y, (float)tv.z, (float)tv.w };
    float AD[4] = { ad.x, ad.y, ad.z, ad.w };

    float acc[12];
    #pragma unroll
    for (int k = 0; k < 12; ++k) acc[k] = 0.f;

    #pragma unroll
    for (int e = 0; e < 4; ++e) {
        float t = T[e];
        float w = 1.f + cfl * __expf(-AD[e] * inv3);
        float tw = t * w;
        float al = (t == 1.f) ? 0.25f : 0.75f;
        float s12 = 1.f - 2.f * t;
        #pragma unroll
        for (int k = 0; k < 4; ++k) {
            float x = X[e][k];
            float y = (t == 1.f) ? -x : x;
            float a = __expf(-fabsf(y));
            float ce = fmaxf(y, 0.f) + __logf(1.f + a);
            float r = __fdividef(1.f, 1.f + a);
            float q = ((y >= 0.f) ? 1.f : a) * r;     // sigmoid(y) = 1 - p_t
            acc[k] += al * q * q * ce;                 // focal
            float p = t + s12 * q;                     // sigmoid(x)
            float pw = p * w;
            acc[4 + k] += pw * t;                      // inter
            acc[8 + k] += pw + tw;                     // (p + t) * w
        }
    }

    #pragma unroll
    for (int k = 0; k < 12; ++k) {
        #pragma unroll
        for (int o = 16; o; o >>= 1)
            acc[k] += __shfl_down_sync(0xffffffffu, acc[k], o);
    }
    __shared__ float sred[8][12];
    if (lane == 0) {
        #pragma unroll
        for (int k = 0; k < 12; ++k) sred[wq][k] = acc[k];
    }
    __syncthreads();
    if (tid < 12) {
        float s = 0.f;
        #pragma unroll
        for (int q = 0; q < 8; ++q) s += sred[q][tid];
        g_part[blk * 12 + tid] = s;
    }

    // --- last-block final combine (threadfence reduction pattern) ---
    __threadfence();
    __syncthreads();
    __shared__ unsigned ticket;
    if (tid == 0) ticket = atomicAdd(&g_ctr, 1u);
    __syncthreads();
    if (ticket == NLB - 1) {
        __threadfence();
        final_combine(out, tid, lane, wq);
    }
}

extern "C" void kernel_launch(void* const* d_in, const int* in_sizes, int n_in,
                              void* d_out, int out_size) {
    const float* p0 = (const float*)d_in[0];   // pred_main
    const float* p1 = (const float*)d_in[1];   // aux0
    const float* p2 = (const float*)d_in[2];   // aux1
    const float* p3 = (const float*)d_in[3];   // aux2
    const int*   tg = (const int*)d_in[4];     // targets

    k_pack <<<128, 128>>>(tg);
    k_edt  <<<NB * NH, 256>>>();
    k_loss <<<NLB, 256>>>(p0, p1, p2, p3, tg, (float*)d_out);
}

// round 7
// speedup vs baseline: 1.1909x; 1.1909x over previous
#include <cuda_runtime.h>
#include <math.h>

#define NB 8
#define NH 256
#define NW 256
#define NPIX (NB*NH*NW)
#define NCH 8              // 8 chunks of 32 rows
#define BLKB 64            // k_loss blocks per batch
#define NLB (NB*BLKB)      // 512 loss blocks

// Scratch (__device__ globals per allocation rules)
__device__ unsigned g_bits[NB*NCH*NW];   // bit i of [b][c][j] = (mask(c*32+i, j) != 0)
__device__ float    g_absd[NPIX];        // |dist| = fgd + bgd (one of them is 0)
__device__ float2   g_rowmax[NB*NH];     // per-row (fg_max, bg_max)
__device__ float    g_part[NLB*12];      // per-block partials: [0:4) focal, [4:8) inter, [8:12) (p+t)w

// ---------------------------------------------------------------------------
// Pack mask into per-column bitsets via warp ballot transpose.
// 128 blocks x 128 threads = 512 warps; one warp per 32x32 tile. MLP=32 loads.
__global__ void k_pack(const int* __restrict__ tg) {
    int w    = blockIdx.x * 4 + (threadIdx.x >> 5);  // 512 warps
    int lane = threadIdx.x & 31;
    int b = w >> 6, rem = w & 63, c = rem >> 3, jg = rem & 7;
    int j = jg * 32 + lane;
    const int* base = tg + (b * NH + c * 32) * NW + j;
    int v[32];
    #pragma unroll
    for (int i = 0; i < 32; ++i) v[i] = __ldg(base + i * NW);
    unsigned word = 0u;
    #pragma unroll
    for (int i = 0; i < 32; ++i) {
        unsigned bal = __ballot_sync(0xffffffffu, v[i] != 0);
        word |= ((bal >> lane) & 1u) << i;
    }
    g_bits[(b * NCH + c) * NW + j] = word;
}

// ---------------------------------------------------------------------------
// EDT: one block per (b, h) row. Vertical distance from a register-resident
// 256-bit column mask (fully unrolled, predicated, no smem for the bitset).
__global__ void k_edt() {
    int blk = blockIdx.x;
    int b = blk >> 8, h = blk & 255;
    int jo = threadIdx.x;
    __shared__ float sf[NW], sb[NW];

    unsigned r[NCH];
    #pragma unroll
    for (int c = 0; c < NCH; ++c)
        r[c] = g_bits[(b * NCH + c) * NW + jo];

    int c0 = h >> 5, b0 = h & 31;
    unsigned upmask = 0xFFFFFFFFu >> (31 - b0);
    unsigned dnmask = 0xFFFFFFFFu << b0;

    // nearest set-bit index <= h (bg uses bits, fg uses complemented bits)
    int bu_b = -100000, bu_f = -100000;
    #pragma unroll
    for (int c = 0; c < NCH; ++c) {
        unsigned wb = r[c];
        unsigned wf = ~r[c];
        if (c == c0) { wb &= upmask; wf &= upmask; }
        if (c >  c0) { wb = 0u; wf = 0u; }
        if (wb) bu_b = c * 32 + 31 - __clz(wb);
        if (wf) bu_f = c * 32 + 31 - __clz(wf);
    }
    // nearest set-bit index >= h
    int bd_b = 100000, bd_f = 100000;
    #pragma unroll
    for (int c = NCH - 1; c >= 0; --c) {
        unsigned wb = r[c];
        unsigned wf = ~r[c];
        if (c == c0) { wb &= dnmask; wf &= dnmask; }
        if (c <  c0) { wb = 0u; wf = 0u; }
        if (wb) bd_b = c * 32 + __ffs(wb) - 1;
        if (wf) bd_f = c * 32 + __ffs(wf) - 1;
    }
    int df = min(h - bu_f, bd_f - h);
    int db = min(h - bu_b, bd_b - h);
    float gf = (df >= 99000) ? 1e6f : (float)df;   // fg: mask==0 feature
    float gb = (db >= 99000) ? 1e6f : (float)db;   // bg: mask==1 feature

    sf[jo] = gf;
    sb[jo] = gb;
    __syncthreads();

    float bf = gf * gf;
    float bb = gb * gb;
    for (int rr = 1; rr < NW; ++rr) {
        float c = (float)(rr * rr);
        if (c >= bf && c >= bb) break;
        int jl = jo - rr, jr = jo + rr;
        if (jl >= 0) {
            float a = sf[jl], x = sb[jl];
            bf = fminf(bf, a * a + c);
            bb = fminf(bb, x * x + c);
        }
        if (jr < NW) {
            float a = sf[jr], x = sb[jr];
            bf = fminf(bf, a * a + c);
            bb = fminf(bb, x * x + c);
        }
    }
    float fgd = sqrtf(bf);
    float bgd = sqrtf(bb);
    g_absd[(b * NH + h) * NW + jo] = fgd + bgd;

    float mf = fgd, mb = bgd;
    #pragma unroll
    for (int o = 16; o; o >>= 1) {
        mf = fmaxf(mf, __shfl_down_sync(0xffffffffu, mf, o));
        mb = fmaxf(mb, __shfl_down_sync(0xffffffffu, mb, o));
    }
    __shared__ float smf[8], smb[8];
    int lane = jo & 31, wq = jo >> 5;
    if (lane == 0) { smf[wq] = mf; smb[wq] = mb; }
    __syncthreads();
    if (jo == 0) {
        #pragma unroll
        for (int q = 1; q < 8; ++q) { mf = fmaxf(mf, smf[q]); mb = fmaxf(mb, smb[q]); }
        g_rowmax[blk] = make_float2(mf, mb);
    }
}

// ---------------------------------------------------------------------------
// Fused focal + IoU partials. 64 blocks per batch, 4 pixels per thread (float4).
__global__ void k_loss(const float* __restrict__ p0, const float* __restrict__ p1,
                       const float* __restrict__ p2, const float* __restrict__ p3,
                       const int* __restrict__ tg) {
    int blk = blockIdx.x;
    int b = blk >> 6;
    int tid = threadIdx.x;
    int lane = tid & 31, wq = tid >> 5;

    // batch maxima from per-row maxima (deterministic)
    __shared__ float sA[8], sB[8];
    {
        float2 rm = g_rowmax[b * NH + tid];
        float mf = rm.x, mb = rm.y;
        #pragma unroll
        for (int o = 16; o; o >>= 1) {
            mf = fmaxf(mf, __shfl_down_sync(0xffffffffu, mf, o));
            mb = fmaxf(mb, __shfl_down_sync(0xffffffffu, mb, o));
        }
        if (lane == 0) { sA[wq] = mf; sB[wq] = mb; }
    }
    __syncthreads();
    float mf = sA[0], mb = sB[0];
    #pragma unroll
    for (int q = 1; q < 8; ++q) { mf = fmaxf(mf, sA[q]); mb = fmaxf(mb, sB[q]); }
    float md = fmaxf(mf, mb);
    bool valid = (mb < 9e5f) && (md > 0.f);
    float inv3 = valid ? 3.0f / fmaxf(md, 1e-12f) : 0.f;
    float cfl  = valid ? 1.f : 0.f;

    int pix = b * (NH * NW) + (blk & 63) * 1024 + tid * 4;
    float4 x0 = *(const float4*)(p0 + pix);
    float4 x1 = *(const float4*)(p1 + pix);
    float4 x2 = *(const float4*)(p2 + pix);
    float4 x3 = *(const float4*)(p3 + pix);
    int4   tv = *(const int4*)(tg + pix);
    float4 ad = *(const float4*)(g_absd + pix);

    float X[4][4] = { {x0.x, x1.x, x2.x, x3.x},
                      {x0.y, x1.y, x2.y, x3.y},
                      {x0.z, x1.z, x2.z, x3.z},
                      {x0.w, x1.w, x2.w, x3.w} };
    float T[4]  = { (float)tv.x, (float)tv.y, (float)tv.z, (float)tv.w };
    float AD[4] = { ad.x, ad.y, ad.z, ad.w };

    float acc[12];
    #pragma unroll
    for (int k = 0; k < 12; ++k) acc[k] = 0.f;

    #pragma unroll
    for (int e = 0; e < 4; ++e) {
        float t = T[e];
        float w = 1.f + cfl * __expf(-AD[e] * inv3);
        float tw = t * w;
        float al = (t == 1.f) ? 0.25f : 0.75f;
        float s12 = 1.f - 2.f * t;
        #pragma unroll
        for (int k = 0; k < 4; ++k) {
            float x = X[e][k];
            float y = (t == 1.f) ? -x : x;
            float a = __expf(-fabsf(y));
            float ce = fmaxf(y, 0.f) + __logf(1.f + a);
            float r = __fdividef(1.f, 1.f + a);
            float q = ((y >= 0.f) ? 1.f : a) * r;     // sigmoid(y) = 1 - p_t
            acc[k] += al * q * q * ce;                 // focal
            float p = t + s12 * q;                     // sigmoid(x)
            float pw = p * w;
            acc[4 + k] += pw * t;                      // inter
            acc[8 + k] += pw + tw;                     // (p + t) * w
        }
    }

    #pragma unroll
    for (int k = 0; k < 12; ++k) {
        #pragma unroll
        for (int o = 16; o; o >>= 1)
            acc[k] += __shfl_down_sync(0xffffffffu, acc[k], o);
    }
    __shared__ float sred[8][12];
    if (lane == 0) {
        #pragma unroll
        for (int k = 0; k < 12; ++k) sred[wq][k] = acc[k];
    }
    __syncthreads();
    if (tid < 12) {
        float s = 0.f;
        #pragma unroll
        for (int q = 0; q < 8; ++q) s += sred[q][tid];
        g_part[blk * 12 + tid] = s;
    }
}

// ---------------------------------------------------------------------------
// Final deterministic combine.
__global__ void k_final(float* __restrict__ out) {
    int tid = threadIdx.x;              // 256 threads
    int lane = tid & 31, wq = tid >> 5;

    // IoU: warp wq handles batch wq
    __shared__ float s_iou[NB][4];
    {
        float in_[4] = {0.f,0.f,0.f,0.f}, u_[4] = {0.f,0.f,0.f,0.f};
        for (int r = lane; r < BLKB; r += 32) {
            const float* pp = g_part + (wq * BLKB + r) * 12;
            #pragma unroll
            for (int k = 0; k < 4; ++k) { in_[k] += pp[4 + k]; u_[k] += pp[8 + k]; }
        }
        #pragma unroll
        for (int k = 0; k < 4; ++k) {
            #pragma unroll
            for (int o = 16; o; o >>= 1) {
                in_[k] += __shfl_down_sync(0xffffffffu, in_[k], o);
                u_[k]  += __shfl_down_sync(0xffffffffu, u_[k],  o);
            }
        }
        if (lane == 0) {
            #pragma unroll
            for (int k = 0; k < 4; ++k) {
                float inter = in_[k];
                float un = u_[k] - inter;
                s_iou[wq][k] = (inter + 1e-6f) / (un + 1e-6f);
            }
        }
    }

    // Focal: tree reduce over NLB block-partials
    float f[4] = {0.f,0.f,0.f,0.f};
    for (int i = tid; i < NLB; i += 256) {
        const float* pp = g_part + i * 12;
        #pragma unroll
        for (int k = 0; k < 4; ++k) f[k] += pp[k];
    }
    __shared__ float sf4[4][256];
    #pragma unroll
    for (int k = 0; k < 4; ++k) sf4[k][tid] = f[k];
    __syncthreads();
    for (int s = 128; s; s >>= 1) {
        if (tid < s) {
            #pragma unroll
            for (int k = 0; k < 4; ++k) sf4[k][tid] += sf4[k][tid + s];
        }
        __syncthreads();
    }

    if (tid == 0) {
        const float wgt[4] = { 1.0f, 0.4f, 0.2f, 0.4f / 3.0f };
        float total = 0.f;
        #pragma unroll
        for (int k = 0; k < 4; ++k) {
            float fm = sf4[k][0] / (float)NPIX;
            float is = 0.f;
            #pragma unroll
            for (int b2 = 0; b2 < NB; ++b2) is += s_iou[b2][k];
            float il = 1.f - is / (float)NB;
            total += wgt[k] * (fm + il);
        }
        out[0] = total;
    }
}

extern "C" void kernel_launch(void* const* d_in, const int* in_sizes, int n_in,
                              void* d_out, int out_size) {
    const float* p0 = (const float*)d_in[0];   // pred_main
    const float* p1 = (const float*)d_in[1];   // aux0
    const float* p2 = (const float*)d_in[2];   // aux1
    const float* p3 = (const float*)d_in[3];   // aux2
    const int*   tg = (const int*)d_in[4];     // targets

    k_pack <<<128, 128>>>(tg);
    k_edt  <<<NB * NH, 256>>>();
    k_loss <<<NLB, 256>>>(p0, p1, p2, p3, tg);
    k_final<<<1, 256>>>((float*)d_out);
}

// round 8
// speedup vs baseline: 1.4569x; 1.2234x over previous
#include <cuda_runtime.h>
#include <math.h>

#define NB 8
#define NH 256
#define NW 256
#define NPIX (NB*NH*NW)
#define NCH 8              // 8 chunks of 32 rows
#define BLKB 64            // k_loss blocks per batch
#define NLB (NB*BLKB)      // 512 loss blocks

// Scratch (static __device__ per allocation rules)
__device__ unsigned g_bits[NB*NCH*NW];   // bit i of [b][c][j] = (mask(c*32+i, j) != 0)
__device__ float    g_absd[NPIX];        // |dist| = fgd + bgd (one of them is 0)
__device__ float2   g_rowmax[NB*NH];     // per-row (fg_max, bg_max)
__device__ float    g_part[NLB*12];      // per-block partials: [0:4) focal, [4:8) inter, [8:12) (p+t)w

// ---------------------------------------------------------------------------
// Pack mask into per-column bitsets via warp ballot transpose.
// 128 blocks x 128 threads = 512 warps; one warp per 32x32 tile. MLP=32 loads.
__global__ void k_pack(const int* __restrict__ tg) {
    int w    = blockIdx.x * 4 + (threadIdx.x >> 5);  // 512 warps
    int lane = threadIdx.x & 31;
    int b = w >> 6, rem = w & 63, c = rem >> 3, jg = rem & 7;
    int j = jg * 32 + lane;
    const int* base = tg + (b * NH + c * 32) * NW + j;
    int v[32];
    #pragma unroll
    for (int i = 0; i < 32; ++i) v[i] = __ldg(base + i * NW);
    unsigned word = 0u;
    #pragma unroll
    for (int i = 0; i < 32; ++i) {
        unsigned bal = __ballot_sync(0xffffffffu, v[i] != 0);
        word |= ((bal >> lane) & 1u) << i;
    }
    g_bits[(b * NCH + c) * NW + j] = word;
}

// Vertical distance to nearest set bit (after XOR with inv) in column jo at row h.
__device__ __forceinline__ float vdist(const unsigned* sw, int jo, int h,
                                       int c0, int b0, unsigned inv) {
    unsigned m = (sw[c0 * NW + jo] ^ inv) & (0xFFFFFFFFu >> (31 - b0));
    int c = c0;
    while (m == 0u && c > 0) m = sw[--c * NW + jo] ^ inv;
    int du = m ? h - (c * 32 + 31 - __clz(m)) : 100000;
    m = (sw[c0 * NW + jo] ^ inv) & (0xFFFFFFFFu << b0);
    c = c0;
    while (m == 0u && c < NCH - 1) m = sw[++c * NW + jo] ^ inv;
    int dd = m ? (c * 32 + __ffs(m) - 1) - h : 100000;
    int d = min(du, dd);
    return (d >= 100000) ? 1e6f : (float)d;
}

// ---------------------------------------------------------------------------
// EDT: one block per (b, h) row (max parallelism).
__global__ void k_edt() {
    int blk = blockIdx.x;
    int b = blk >> 8, h = blk & 255;
    int jo = threadIdx.x;
    __shared__ unsigned sw[NCH * NW];
    __shared__ float sf[NW], sb[NW];
    #pragma unroll
    for (int c = 0; c < NCH; ++c)
        sw[c * NW + jo] = g_bits[(b * NCH + c) * NW + jo];
    __syncthreads();

    int c0 = h >> 5, b0 = h & 31;
    float gf = vdist(sw, jo, h, c0, b0, 0xFFFFFFFFu);  // fg: mask==0
    float gb = vdist(sw, jo, h, c0, b0, 0u);           // bg: mask==1
    sf[jo] = gf;
    sb[jo] = gb;
    __syncthreads();

    float bf = gf * gf;
    float bb = gb * gb;
    for (int r = 1; r < NW; ++r) {
        float c = (float)(r * r);
        if (c >= bf && c >= bb) break;
        int jl = jo - r, jr = jo + r;
        if (jl >= 0) {
            float a = sf[jl], x = sb[jl];
            bf = fminf(bf, a * a + c);
            bb = fminf(bb, x * x + c);
        }
        if (jr < NW) {
            float a = sf[jr], x = sb[jr];
            bf = fminf(bf, a * a + c);
            bb = fminf(bb, x * x + c);
        }
    }
    float fgd = sqrtf(bf);
    float bgd = sqrtf(bb);
    g_absd[(b * NH + h) * NW + jo] = fgd + bgd;

    // deterministic per-row max -> g_rowmax
    float mf = fgd, mb = bgd;
    #pragma unroll
    for (int o = 16; o; o >>= 1) {
        mf = fmaxf(mf, __shfl_down_sync(0xffffffffu, mf, o));
        mb = fmaxf(mb, __shfl_down_sync(0xffffffffu, mb, o));
    }
    __shared__ float smf[8], smb[8];
    int lane = jo & 31, wq = jo >> 5;
    if (lane == 0) { smf[wq] = mf; smb[wq] = mb; }
    __syncthreads();
    if (jo == 0) {
        #pragma unroll
        for (int q = 1; q < 8; ++q) { mf = fmaxf(mf, smf[q]); mb = fmaxf(mb, smb[q]); }
        g_rowmax[blk] = make_float2(mf, mb);
    }
}

// ---------------------------------------------------------------------------
// Fused focal + IoU partials. 64 blocks per batch, 4 pixels per thread (float4).
__global__ void k_loss(const float* __restrict__ p0, const float* __restrict__ p1,
                       const float* __restrict__ p2, const float* __restrict__ p3,
                       const int* __restrict__ tg) {
    int blk = blockIdx.x;
    int b = blk >> 6;
    int tid = threadIdx.x;
    int lane = tid & 31, wq = tid >> 5;

    // batch maxima from per-row maxima (deterministic)
    __shared__ float sA[8], sB[8];
    {
        float2 rm = g_rowmax[b * NH + tid];
        float mf = rm.x, mb = rm.y;
        #pragma unroll
        for (int o = 16; o; o >>= 1) {
            mf = fmaxf(mf, __shfl_down_sync(0xffffffffu, mf, o));
            mb = fmaxf(mb, __shfl_down_sync(0xffffffffu, mb, o));
        }
        if (lane == 0) { sA[wq] = mf; sB[wq] = mb; }
    }
    __syncthreads();
    float mf = sA[0], mb = sB[0];
    #pragma unroll
    for (int q = 1; q < 8; ++q) { mf = fmaxf(mf, sA[q]); mb = fmaxf(mb, sB[q]); }
    float md = fmaxf(mf, mb);
    bool valid = (mb < 9e5f) && (md > 0.f);
    float inv3 = valid ? 3.0f / fmaxf(md, 1e-12f) : 0.f;
    float cfl  = valid ? 1.f : 0.f;

    int pix = b * (NH * NW) + (blk & 63) * 1024 + tid * 4;
    float4 x0 = *(const float4*)(p0 + pix);
    float4 x1 = *(const float4*)(p1 + pix);
    float4 x2 = *(const float4*)(p2 + pix);
    float4 x3 = *(const float4*)(p3 + pix);
    int4   tv = *(const int4*)(tg + pix);
    float4 ad = *(const float4*)(g_absd + pix);

    float X[4][4] = { {x0.x, x1.x, x2.x, x3.x},
                      {x0.y, x1.y, x2.y, x3.y},
                      {x0.z, x1.z, x2.z, x3.z},
                      {x0.w, x1.w, x2.w, x3.w} };
    float T[4]  = { (float)tv.x, (float)tv.y, (float)tv.z, (float)tv.w };
    float AD[4] = { ad.x, ad.y, ad.z, ad.w };

    float acc[12];
    #pragma unroll
    for (int k = 0; k < 12; ++k) acc[k] = 0.f;

    #pragma unroll
    for (int e = 0; e < 4; ++e) {
        float t = T[e];
        float w = 1.f + cfl * __expf(-AD[e] * inv3);
        float tw = t * w;
        float al = (t == 1.f) ? 0.25f : 0.75f;
        float s12 = 1.f - 2.f * t;
        #pragma unroll
        for (int k = 0; k < 4; ++k) {
            float x = X[e][k];
            float y = (t == 1.f) ? -x : x;
            float a = __expf(-fabsf(y));
            float ce = fmaxf(y, 0.f) + __logf(1.f + a);
            float r = __fdividef(1.f, 1.f + a);
            float q = ((y >= 0.f) ? 1.f : a) * r;     // sigmoid(y) = 1 - p_t
            acc[k] += al * q * q * ce;                 // focal
            float p = t + s12 * q;                     // sigmoid(x)
            float pw = p * w;
            acc[4 + k] += pw * t;                      // inter
            acc[8 + k] += pw + tw;                     // (p + t) * w
        }
    }

    #pragma unroll
    for (int k = 0; k < 12; ++k) {
        #pragma unroll
        for (int o = 16; o; o >>= 1)
            acc[k] += __shfl_down_sync(0xffffffffu, acc[k], o);
    }
    __shared__ float sred[8][12];
    if (lane == 0) {
        #pragma unroll
        for (int k = 0; k < 12; ++k) sred[wq][k] = acc[k];
    }
    __syncthreads();
    if (tid < 12) {
        float s = 0.f;
        #pragma unroll
        for (int q = 0; q < 8; ++q) s += sred[q][tid];
        g_part[blk * 12 + tid] = s;
    }
}

// ---------------------------------------------------------------------------
// Final deterministic combine.
__global__ void k_final(float* __restrict__ out) {
    int tid = threadIdx.x;              // 256 threads
    int lane = tid & 31, wq = tid >> 5;

    // IoU: warp wq handles batch wq
    __shared__ float s_iou[NB][4];
    {
        float in_[4] = {0.f,0.f,0.f,0.f}, u_[4] = {0.f,0.f,0.f,0.f};
        for (int r = lane; r < BLKB; r += 32) {
            const float* pp = g_part + (wq * BLKB + r) * 12;
            #pragma unroll
            for (int k = 0; k < 4; ++k) { in_[k] += pp[4 + k]; u_[k] += pp[8 + k]; }
        }
        #pragma unroll
        for (int k = 0; k < 4; ++k) {
            #pragma unroll
            for (int o = 16; o; o >>= 1) {
                in_[k] += __shfl_down_sync(0xffffffffu, in_[k], o);
                u_[k]  += __shfl_down_sync(0xffffffffu, u_[k],  o);
            }
        }
        if (lane == 0) {
            #pragma unroll
            for (int k = 0; k < 4; ++k) {
                float inter = in_[k];
                float un = u_[k] - inter;
                s_iou[wq][k] = (inter + 1e-6f) / (un + 1e-6f);
            }
        }
    }

    // Focal: tree reduce over NLB block-partials
    float f[4] = {0.f,0.f,0.f,0.f};
    for (int i = tid; i < NLB; i += 256) {
        const float* pp = g_part + i * 12;
        #pragma unroll
        for (int k = 0; k < 4; ++k) f[k] += pp[k];
    }
    __shared__ float sf4[4][256];
    #pragma unroll
    for (int k = 0; k < 4; ++k) sf4[k][tid] = f[k];
    __syncthreads();
    for (int s = 128; s; s >>= 1) {
        if (tid < s) {
            #pragma unroll
            for (int k = 0; k < 4; ++k) sf4[k][tid] += sf4[k][tid + s];
        }
        __syncthreads();
    }

    if (tid == 0) {
        const float wgt[4] = { 1.0f, 0.4f, 0.2f, 0.4f / 3.0f };
        float total = 0.f;
        #pragma unroll
        for (int k = 0; k < 4; ++k) {
            float fm = sf4[k][0] / (float)NPIX;
            float is = 0.f;
            #pragma unroll
            for (int b2 = 0; b2 < NB; ++b2) is += s_iou[b2][k];
            float il = 1.f - is / (float)NB;
            total += wgt[k] * (fm + il);
        }
        out[0] = total;
    }
}

extern "C" void kernel_launch(void* const* d_in, const int* in_sizes, int n_in,
                              void* d_out, int out_size) {
    const float* p0 = (const float*)d_in[0];   // pred_main
    const float* p1 = (const float*)d_in[1];   // aux0
    const float* p2 = (const float*)d_in[2];   // aux1
    const float* p3 = (const float*)d_in[3];   // aux2
    const int*   tg = (const int*)d_in[4];     // targets

    k_pack <<<128, 128>>>(tg);
    k_edt  <<<NB * NH, 256>>>();
    k_loss <<<NLB, 256>>>(p0, p1, p2, p3, tg);
    k_final<<<1, 256>>>((float*)d_out);
}